// round 2
// baseline (speedup 1.0000x reference)
#include <cuda_runtime.h>
#include <math.h>

#define HW 4096
#define CH 256
#define NB 4
#define NBC (NB*CH)        // 1024

// ---- scratch (static device globals; no allocation) ----
__device__ float g_mean[2 * NBC];
__device__ float g_rstd[2 * NBC];
__device__ float g_Q[(size_t)NB * HW * CH];
__device__ float g_K[(size_t)NB * HW * CH];
__device__ float g_V[(size_t)NB * HW * CH];

// =====================================================================
// Stage 1: per-(b,c) mean / rstd for content (idx 0..1023) and style
// (idx 1024..2047). var is unbiased (ddof=1), +1e-5 inside sqrt.
// =====================================================================
__global__ void stats_kernel(const float* __restrict__ content,
                             const float* __restrict__ style) {
    int id = blockIdx.x;                              // 0..2047
    const float* base = (id < NBC ? content : style) + (size_t)(id & (NBC - 1)) * HW;
    float s = 0.f, s2 = 0.f;
    const float4* b4 = (const float4*)base;
    for (int i = threadIdx.x; i < HW / 4; i += 256) {
        float4 v = b4[i];
        s  += v.x + v.y + v.z + v.w;
        s2 += v.x * v.x + v.y * v.y + v.z * v.z + v.w * v.w;
    }
    #pragma unroll
    for (int o = 16; o; o >>= 1) {
        s  += __shfl_xor_sync(~0u, s, o);
        s2 += __shfl_xor_sync(~0u, s2, o);
    }
    __shared__ float sh[8][2];
    int w = threadIdx.x >> 5, l = threadIdx.x & 31;
    if (l == 0) { sh[w][0] = s; sh[w][1] = s2; }
    __syncthreads();
    if (threadIdx.x == 0) {
        s = 0.f; s2 = 0.f;
        #pragma unroll
        for (int i = 0; i < 8; i++) { s += sh[i][0]; s2 += sh[i][1]; }
        float m   = s / (float)HW;
        float var = (s2 - (float)HW * m * m) / (float)(HW - 1);
        g_mean[id] = m;
        g_rstd[id] = rsqrtf(var + 1e-5f);
    }
}

// =====================================================================
// Stage 2: Q/K/V GEMMs. Out[p][o] = sum_c W[o][c] * Xn[c][p] + bias[o]
// Xn is normalized on load (identity for V). Block tile 128p x 64o,
// 256 threads, 8x4 micro-tile, k-chunks of 32.
// =====================================================================
__global__ __launch_bounds__(256) void qkv_gemm(
    const float* __restrict__ content, const float* __restrict__ style,
    const float* __restrict__ Wf, const float* __restrict__ bf,
    const float* __restrict__ Wg, const float* __restrict__ bg,
    const float* __restrict__ Wh, const float* __restrict__ bh)
{
    int z   = blockIdx.z;
    int mat = z % 3, b = z / 3;
    const float *X, *W, *bias;
    float* out;
    int soff;
    if (mat == 0)      { X = content; W = Wf; bias = bf; soff = 0;   out = g_Q; }
    else if (mat == 1) { X = style;   W = Wg; bias = bg; soff = NBC; out = g_K; }
    else               { X = style;   W = Wh; bias = bh; soff = -1;  out = g_V; }
    X   += (size_t)b * CH * HW;
    out += (size_t)b * HW * CH;
    int p0 = blockIdx.x * 128, o0 = blockIdx.y * 64;

    __shared__ float Xs[32][132];   // [channel][pixel], padded
    __shared__ float Ws[64][36];    // [o][channel], padded

    int tid = threadIdx.x;
    int tx  = tid & 15, ty = tid >> 4;    // tx -> pixel octet, ty -> o quad
    float acc[8][4];
    #pragma unroll
    for (int u = 0; u < 8; u++)
        #pragma unroll
        for (int v = 0; v < 4; v++) acc[u][v] = 0.f;

    for (int c0 = 0; c0 < CH; c0 += 32) {
        __syncthreads();
        // X tile (normalized)
        #pragma unroll
        for (int r = 0; r < 4; r++) {
            int e = tid + 256 * r;                 // 0..1023 float4 units
            int row = e >> 5, c4 = e & 31;
            float4 v = *(const float4*)(X + (size_t)(c0 + row) * HW + p0 + c4 * 4);
            if (soff >= 0) {
                float m  = g_mean[soff + b * CH + c0 + row];
                float rs = g_rstd[soff + b * CH + c0 + row];
                v.x = (v.x - m) * rs; v.y = (v.y - m) * rs;
                v.z = (v.z - m) * rs; v.w = (v.w - m) * rs;
            }
            *(float4*)&Xs[row][c4 * 4] = v;
        }
        // W tile
        #pragma unroll
        for (int r = 0; r < 2; r++) {
            int e = tid + 256 * r;                 // 0..511 float4 units
            int row = e >> 3, c4 = e & 7;
            *(float4*)&Ws[row][c4 * 4] =
                *(const float4*)(W + (size_t)(o0 + row) * CH + c0 + c4 * 4);
        }
        __syncthreads();
        #pragma unroll
        for (int cc = 0; cc < 32; cc++) {
            float4 x0 = *(float4*)&Xs[cc][tx * 8];
            float4 x1 = *(float4*)&Xs[cc][tx * 8 + 4];
            float w0 = Ws[ty * 4 + 0][cc], w1 = Ws[ty * 4 + 1][cc];
            float w2 = Ws[ty * 4 + 2][cc], w3 = Ws[ty * 4 + 3][cc];
            float xv[8] = {x0.x, x0.y, x0.z, x0.w, x1.x, x1.y, x1.z, x1.w};
            #pragma unroll
            for (int u = 0; u < 8; u++) {
                acc[u][0] += xv[u] * w0;
                acc[u][1] += xv[u] * w1;
                acc[u][2] += xv[u] * w2;
                acc[u][3] += xv[u] * w3;
            }
        }
    }
    float b0 = bias[o0 + ty * 4 + 0], b1 = bias[o0 + ty * 4 + 1];
    float b2 = bias[o0 + ty * 4 + 2], b3 = bias[o0 + ty * 4 + 3];
    #pragma unroll
    for (int u = 0; u < 8; u++) {
        float4 ov = make_float4(acc[u][0] + b0, acc[u][1] + b1,
                                acc[u][2] + b2, acc[u][3] + b3);
        *(float4*)(out + (size_t)(p0 + tx * 8 + u) * CH + o0 + ty * 4) = ov;
    }
}

// =====================================================================
// Stage 3: fused flash attention + moments + AdaAttN epilogue.
// 256 threads, M=64 queries/block, N=64 keys/tile, d=256.
// Each warp owns 8 query rows end-to-end (softmax is warp-local).
// Each lane owns an 8-channel slice of the output accumulators.
// =====================================================================
#define MQ   64
#define NT   64
#define QPAD 260
#define PPAD 68

__global__ __launch_bounds__(256, 1) void attn_kernel(
    const float* __restrict__ content, float* __restrict__ out)
{
    extern __shared__ float sm[];
    float* Qs = sm;                       // MQ * QPAD
    float* Ks = Qs + MQ * QPAD;           // NT * QPAD
    float* Vs = Ks + NT * QPAD;           // NT * QPAD
    float* Ps = Vs + NT * QPAD;           // MQ * PPAD

    int b  = blockIdx.y;
    int p0 = blockIdx.x * MQ;
    int tid  = threadIdx.x;
    int wid  = tid >> 5, lane = tid & 31;
    int tx   = tid & 15, ty = tid >> 4;
    int i0   = ty * 4, j0 = tx * 4;       // warp `wid` owns rows 8*wid..8*wid+7
    int d0   = lane * 8;                  // channel slice per lane

    // load Q tile
    const float4* Qg = (const float4*)(g_Q + ((size_t)b * HW + p0) * CH);
    #pragma unroll
    for (int r = 0; r < 16; r++) {
        int e = tid + 256 * r;            // 0..4095 float4 units
        int row = e >> 6, c4 = e & 63;
        *(float4*)&Qs[row * QPAD + c4 * 4] = Qg[row * 64 + c4];
    }

    float O1[8][8], O2[8][8];
    #pragma unroll
    for (int rr = 0; rr < 8; rr++)
        #pragma unroll
        for (int u = 0; u < 8; u++) { O1[rr][u] = 0.f; O2[rr][u] = 0.f; }
    float mrow[8], lrow[8];
    #pragma unroll
    for (int rr = 0; rr < 8; rr++) { mrow[rr] = -1e30f; lrow[rr] = 0.f; }

    for (int kt = 0; kt < HW / NT; kt++) {
        __syncthreads();   // protect Ks/Vs/Ps from previous tile's readers
        const float4* Kg = (const float4*)(g_K + ((size_t)b * HW + kt * NT) * CH);
        const float4* Vg = (const float4*)(g_V + ((size_t)b * HW + kt * NT) * CH);
        #pragma unroll
        for (int r = 0; r < 16; r++) {
            int e = tid + 256 * r;
            int row = e >> 6, c4 = e & 63;
            *(float4*)&Ks[row * QPAD + c4 * 4] = Kg[row * 64 + c4];
            *(float4*)&Vs[row * QPAD + c4 * 4] = Vg[row * 64 + c4];
        }
        __syncthreads();

        // ---- scores: 4x4 per thread ----
        float s[4][4];
        #pragma unroll
        for (int ii = 0; ii < 4; ii++)
            #pragma unroll
            for (int jj = 0; jj < 4; jj++) s[ii][jj] = 0.f;

        #pragma unroll 2
        for (int k = 0; k < CH; k += 4) {
            float4 q[4], kk[4];
            #pragma unroll
            for (int ii = 0; ii < 4; ii++)
                q[ii] = *(const float4*)&Qs[(i0 + ii) * QPAD + k];
            #pragma unroll
            for (int jj = 0; jj < 4; jj++)
                kk[jj] = *(const float4*)&Ks[(j0 + jj) * QPAD + k];
            #pragma unroll
            for (int ii = 0; ii < 4; ii++)
                #pragma unroll
                for (int jj = 0; jj < 4; jj++)
                    s[ii][jj] += q[ii].x * kk[jj].x + q[ii].y * kk[jj].y +
                                 q[ii].z * kk[jj].z + q[ii].w * kk[jj].w;
        }
        #pragma unroll
        for (int ii = 0; ii < 4; ii++)
            #pragma unroll
            for (int jj = 0; jj < 4; jj++)
                Ps[(i0 + ii) * PPAD + j0 + jj] = s[ii][jj];
        __syncwarp();      // Ps rows 8*wid..+7 are written only by this warp

        // ---- warp-local online softmax over this warp's 8 rows ----
        #pragma unroll
        for (int rr = 0; rr < 8; rr++) {
            int r = wid * 8 + rr;
            float s0 = Ps[r * PPAD + lane];
            float s1 = Ps[r * PPAD + 32 + lane];
            float mx = fmaxf(s0, s1);
            #pragma unroll
            for (int o = 16; o; o >>= 1) mx = fmaxf(mx, __shfl_xor_sync(~0u, mx, o));
            float mnew = fmaxf(mrow[rr], mx);
            float corr = __expf(mrow[rr] - mnew);
            float e0 = __expf(s0 - mnew);
            float e1 = __expf(s1 - mnew);
            float rs = e0 + e1;
            #pragma unroll
            for (int o = 16; o; o >>= 1) rs += __shfl_xor_sync(~0u, rs, o);
            lrow[rr] = lrow[rr] * corr + rs;
            mrow[rr] = mnew;
            Ps[r * PPAD + lane]      = e0;
            Ps[r * PPAD + 32 + lane] = e1;
            #pragma unroll
            for (int u = 0; u < 8; u++) { O1[rr][u] *= corr; O2[rr][u] *= corr; }
        }
        __syncwarp();

        // ---- P @ [V, V^2] ----
        #pragma unroll 2
        for (int j = 0; j < NT; j++) {
            const float* vrow = &Vs[j * QPAD + d0];
            float4 v0 = *(const float4*)vrow;
            float4 v1 = *(const float4*)(vrow + 4);
            float4 q0, q1;
            q0.x = v0.x * v0.x; q0.y = v0.y * v0.y; q0.z = v0.z * v0.z; q0.w = v0.w * v0.w;
            q1.x = v1.x * v1.x; q1.y = v1.y * v1.y; q1.z = v1.z * v1.z; q1.w = v1.w * v1.w;
            const float* prow = &Ps[(wid * 8) * PPAD + j];
            #pragma unroll
            for (int rr = 0; rr < 8; rr++) {
                float p = prow[rr * PPAD];
                O1[rr][0] += p * v0.x; O1[rr][1] += p * v0.y;
                O1[rr][2] += p * v0.z; O1[rr][3] += p * v0.w;
                O1[rr][4] += p * v1.x; O1[rr][5] += p * v1.y;
                O1[rr][6] += p * v1.z; O1[rr][7] += p * v1.w;
                O2[rr][0] += p * q0.x; O2[rr][1] += p * q0.y;
                O2[rr][2] += p * q0.z; O2[rr][3] += p * q0.w;
                O2[rr][4] += p * q1.x; O2[rr][5] += p * q1.y;
                O2[rr][6] += p * q1.z; O2[rr][7] += p * q1.w;
            }
        }
    }

    // ---- epilogue: mean/std/out, layout [b,c,h,w]; outputs concatenated ----
    const size_t TSZ = (size_t)NB * CH * HW;
    int boff = b * CH;
    #pragma unroll
    for (int rr = 0; rr < 8; rr++) {
        int p = p0 + wid * 8 + rr;
        float rn = 1.0f / lrow[rr];
        #pragma unroll
        for (int u = 0; u < 8; u++) {
            int c = d0 + u;
            float mean = O1[rr][u] * rn;
            float sec  = O2[rr][u] * rn;
            float var  = sec - mean * mean;
            float sd   = sqrtf(fmaxf(var, 0.f));
            size_t idx = (size_t)(boff + c) * HW + p;
            float nc = (content[idx] - g_mean[boff + c]) * g_rstd[boff + c];
            out[idx]           = sd * nc + mean;
            out[idx + TSZ]     = mean;
            out[idx + 2 * TSZ] = sd;
        }
    }
}

// =====================================================================
extern "C" void kernel_launch(void* const* d_in, const int* in_sizes, int n_in,
                              void* d_out, int out_size) {
    const float* content = (const float*)d_in[0];
    const float* style   = (const float*)d_in[1];
    const float* Wf = (const float*)d_in[2];
    const float* bf = (const float*)d_in[3];
    const float* Wg = (const float*)d_in[4];
    const float* bg = (const float*)d_in[5];
    const float* Wh = (const float*)d_in[6];
    const float* bh = (const float*)d_in[7];
    float* out = (float*)d_out;

    stats_kernel<<<2 * NBC, 256>>>(content, style);
    qkv_gemm<<<dim3(HW / 128, CH / 64, 3 * NB), 256>>>(content, style,
                                                       Wf, bf, Wg, bg, Wh, bh);
    const int smem = (MQ * QPAD + 2 * NT * QPAD + MQ * PPAD) * (int)sizeof(float);
    static bool attr_set = false;
    if (!attr_set) {
        cudaFuncSetAttribute(attn_kernel,
                             cudaFuncAttributeMaxDynamicSharedMemorySize, smem);
        attr_set = true;
    }
    attn_kernel<<<dim3(HW / MQ, NB), 256, smem>>>(content, out);
}

// round 3
// speedup vs baseline: 2.5434x; 2.5434x over previous
#include <cuda_runtime.h>
#include <math.h>
#include <stdint.h>

#define HW 4096
#define CH 256
#define NB 4
#define NBC (NB*CH)        // 1024

// ---- scratch (static device globals; no allocation) ----
__device__ float g_mean[2 * NBC];
__device__ float g_rstd[2 * NBC];
__device__ float g_Q[(size_t)NB * HW * CH];
__device__ float g_K[(size_t)NB * HW * CH];
__device__ float g_V[(size_t)NB * HW * CH];

// ---------------- packed f32x2 helpers (sm_103a) ----------------
__device__ __forceinline__ unsigned long long ffma2(unsigned long long a,
                                                    unsigned long long b,
                                                    unsigned long long c) {
    unsigned long long d;
    asm("fma.rn.f32x2 %0, %1, %2, %3;" : "=l"(d) : "l"(a), "l"(b), "l"(c));
    return d;
}
__device__ __forceinline__ unsigned long long fmul2(unsigned long long a,
                                                    unsigned long long b) {
    unsigned long long d;
    asm("mul.rn.f32x2 %0, %1, %2;" : "=l"(d) : "l"(a), "l"(b));
    return d;
}
__device__ __forceinline__ unsigned long long fpack2(float x) {
    unsigned long long d;
    unsigned int xi = __float_as_uint(x);
    asm("mov.b64 %0, {%1, %1};" : "=l"(d) : "r"(xi));
    return d;
}
__device__ __forceinline__ float2 funpack(unsigned long long v) {
    unsigned int lo, hi;
    asm("mov.b64 {%0, %1}, %2;" : "=r"(lo), "=r"(hi) : "l"(v));
    float2 r; r.x = __uint_as_float(lo); r.y = __uint_as_float(hi);
    return r;
}
__device__ __forceinline__ void cpa16(unsigned int dst, const void* src) {
    asm volatile("cp.async.cg.shared.global [%0], [%1], 16;" :: "r"(dst), "l"(src));
}
__device__ __forceinline__ void cpa_commit() {
    asm volatile("cp.async.commit_group;");
}
__device__ __forceinline__ void cpa_wait0() {
    asm volatile("cp.async.wait_group 0;");
}

// =====================================================================
// Stage 1: per-(b,c) mean / rstd for content (idx 0..1023) and style
// (idx 1024..2047). var is unbiased (ddof=1), +1e-5 inside sqrt.
// =====================================================================
__global__ void stats_kernel(const float* __restrict__ content,
                             const float* __restrict__ style) {
    int id = blockIdx.x;                              // 0..2047
    const float* base = (id < NBC ? content : style) + (size_t)(id & (NBC - 1)) * HW;
    float s = 0.f, s2 = 0.f;
    const float4* b4 = (const float4*)base;
    for (int i = threadIdx.x; i < HW / 4; i += 256) {
        float4 v = b4[i];
        s  += v.x + v.y + v.z + v.w;
        s2 += v.x * v.x + v.y * v.y + v.z * v.z + v.w * v.w;
    }
    #pragma unroll
    for (int o = 16; o; o >>= 1) {
        s  += __shfl_xor_sync(~0u, s, o);
        s2 += __shfl_xor_sync(~0u, s2, o);
    }
    __shared__ float sh[8][2];
    int w = threadIdx.x >> 5, l = threadIdx.x & 31;
    if (l == 0) { sh[w][0] = s; sh[w][1] = s2; }
    __syncthreads();
    if (threadIdx.x == 0) {
        s = 0.f; s2 = 0.f;
        #pragma unroll
        for (int i = 0; i < 8; i++) { s += sh[i][0]; s2 += sh[i][1]; }
        float m   = s / (float)HW;
        float var = (s2 - (float)HW * m * m) / (float)(HW - 1);
        g_mean[id] = m;
        g_rstd[id] = rsqrtf(var + 1e-5f);
    }
}

// =====================================================================
// Stage 2: Q/K/V GEMMs (unchanged from passing version).
// =====================================================================
__global__ __launch_bounds__(256) void qkv_gemm(
    const float* __restrict__ content, const float* __restrict__ style,
    const float* __restrict__ Wf, const float* __restrict__ bf,
    const float* __restrict__ Wg, const float* __restrict__ bg,
    const float* __restrict__ Wh, const float* __restrict__ bh)
{
    int z   = blockIdx.z;
    int mat = z % 3, b = z / 3;
    const float *X, *W, *bias;
    float* out;
    int soff;
    if (mat == 0)      { X = content; W = Wf; bias = bf; soff = 0;   out = g_Q; }
    else if (mat == 1) { X = style;   W = Wg; bias = bg; soff = NBC; out = g_K; }
    else               { X = style;   W = Wh; bias = bh; soff = -1;  out = g_V; }
    X   += (size_t)b * CH * HW;
    out += (size_t)b * HW * CH;
    int p0 = blockIdx.x * 128, o0 = blockIdx.y * 64;

    __shared__ float Xs[32][132];   // [channel][pixel], padded
    __shared__ float Ws[64][36];    // [o][channel], padded

    int tid = threadIdx.x;
    int tx  = tid & 15, ty = tid >> 4;
    float acc[8][4];
    #pragma unroll
    for (int u = 0; u < 8; u++)
        #pragma unroll
        for (int v = 0; v < 4; v++) acc[u][v] = 0.f;

    for (int c0 = 0; c0 < CH; c0 += 32) {
        __syncthreads();
        #pragma unroll
        for (int r = 0; r < 4; r++) {
            int e = tid + 256 * r;
            int row = e >> 5, c4 = e & 31;
            float4 v = *(const float4*)(X + (size_t)(c0 + row) * HW + p0 + c4 * 4);
            if (soff >= 0) {
                float m  = g_mean[soff + b * CH + c0 + row];
                float rs = g_rstd[soff + b * CH + c0 + row];
                v.x = (v.x - m) * rs; v.y = (v.y - m) * rs;
                v.z = (v.z - m) * rs; v.w = (v.w - m) * rs;
            }
            *(float4*)&Xs[row][c4 * 4] = v;
        }
        #pragma unroll
        for (int r = 0; r < 2; r++) {
            int e = tid + 256 * r;
            int row = e >> 3, c4 = e & 7;
            *(float4*)&Ws[row][c4 * 4] =
                *(const float4*)(W + (size_t)(o0 + row) * CH + c0 + c4 * 4);
        }
        __syncthreads();
        #pragma unroll
        for (int cc = 0; cc < 32; cc++) {
            float4 x0 = *(float4*)&Xs[cc][tx * 8];
            float4 x1 = *(float4*)&Xs[cc][tx * 8 + 4];
            float w0 = Ws[ty * 4 + 0][cc], w1 = Ws[ty * 4 + 1][cc];
            float w2 = Ws[ty * 4 + 2][cc], w3 = Ws[ty * 4 + 3][cc];
            float xv[8] = {x0.x, x0.y, x0.z, x0.w, x1.x, x1.y, x1.z, x1.w};
            #pragma unroll
            for (int u = 0; u < 8; u++) {
                acc[u][0] += xv[u] * w0;
                acc[u][1] += xv[u] * w1;
                acc[u][2] += xv[u] * w2;
                acc[u][3] += xv[u] * w3;
            }
        }
    }
    float b0 = bias[o0 + ty * 4 + 0], b1 = bias[o0 + ty * 4 + 1];
    float b2 = bias[o0 + ty * 4 + 2], b3 = bias[o0 + ty * 4 + 3];
    #pragma unroll
    for (int u = 0; u < 8; u++) {
        float4 ov = make_float4(acc[u][0] + b0, acc[u][1] + b1,
                                acc[u][2] + b2, acc[u][3] + b3);
        *(float4*)(out + (size_t)(p0 + tx * 8 + u) * CH + o0 + ty * 4) = ov;
    }
}

// =====================================================================
// Stage 3: fused flash attention with packed f32x2 FMAs.
// 256 threads (8 warps). Block handles 2 query tiles of M=64 rows.
// K tile NT=128 keys; Q/K/V tiles in XOR-swizzled smem (float4 groups).
// Scores: thread tile 4 rows x 8 keys, accumulated as f32x2 pairs over
// the channel dim, split into two 4-key half passes (register budget).
// Softmax: warp-local (warp owns rows 8w..8w+7). PV: packed f32x2
// accumulators, V^2 stream fused, V reuses the K smem buffer.
// =====================================================================
#define MQ  64
#define NTK 128
#define PP  132

// float4-group swizzle: logical (row, g) -> physical group
#define SWZ(row, g) (((row) << 6) + ((g) ^ (((row) >> 3) & 7)))

__global__ __launch_bounds__(256, 1) void attn_kernel(
    const float* __restrict__ content, float* __restrict__ out)
{
    extern __shared__ float sm[];
    float* Qs = sm;                    // MQ  * 256
    float* Ks = Qs + MQ * CH;          // NTK * 256 (K, later V)
    float* Ps = Ks + NTK * CH;         // MQ * PP

    unsigned int QsA = (unsigned int)__cvta_generic_to_shared(Qs);
    unsigned int KsA = (unsigned int)__cvta_generic_to_shared(Ks);

    int b    = blockIdx.y;
    int tid  = threadIdx.x;
    int wid  = tid >> 5, lane = tid & 31;
    int tx   = tid & 15, ty = tid >> 4;
    int i0   = ty * 4;                 // 4 query rows per thread (scores)
    int d0   = lane * 8;               // 8-channel slice per lane (PV)

    for (int qt = 0; qt < 2; qt++) {
        int p0 = (blockIdx.x * 2 + qt) * MQ;

        // ---- async-load Q tile (waited inside first kt iteration) ----
        const float4* Qg = (const float4*)(g_Q + ((size_t)b * HW + p0) * CH);
        #pragma unroll
        for (int r = 0; r < 16; r++) {
            int e = tid + 256 * r;     // 4096 float4 slots
            int row = e >> 6, g = e & 63;
            cpa16(QsA + (unsigned int)SWZ(row, g) * 16u, Qg + (size_t)row * 64 + g);
        }
        cpa_commit();

        unsigned long long O1[8][4], O2[8][4];
        #pragma unroll
        for (int rr = 0; rr < 8; rr++)
            #pragma unroll
            for (int u = 0; u < 4; u++) { O1[rr][u] = 0ull; O2[rr][u] = 0ull; }
        float m8[8], l8[8];
        #pragma unroll
        for (int rr = 0; rr < 8; rr++) { m8[rr] = -1e30f; l8[rr] = 0.f; }

        for (int kt = 0; kt < HW / NTK; kt++) {
            __syncthreads();   // prev PV done with Ks(V) and Ps

            // ---- async-load K tile ----
            const float4* Kg = (const float4*)(g_K + ((size_t)b * HW + kt * NTK) * CH);
            #pragma unroll
            for (int r = 0; r < 32; r++) {
                int e = tid + 256 * r;          // 8192 float4 slots
                int row = e >> 6, g = e & 63;
                cpa16(KsA + (unsigned int)SWZ(row, g) * 16u, Kg + (size_t)row * 64 + g);
            }
            cpa_commit();
            cpa_wait0();        // waits Q too on first tile
            __syncthreads();

            // ---- scores: two half passes of 4 rows x 4 keys ----
            #pragma unroll
            for (int jh = 0; jh < 2; jh++) {
                int j0 = tx * 8 + jh * 4;
                const float* qrow[4];
                const float* krow[4];
                int qsw[4], ksw[4];
                #pragma unroll
                for (int ii = 0; ii < 4; ii++) {
                    qrow[ii] = Qs + ((i0 + ii) << 8);
                    qsw[ii]  = ((i0 + ii) >> 3) & 7;
                    krow[ii] = Ks + ((j0 + ii) << 8);
                    ksw[ii]  = ((j0 + ii) >> 3) & 7;
                }
                unsigned long long s2[4][4];
                #pragma unroll
                for (int ii = 0; ii < 4; ii++)
                    #pragma unroll
                    for (int jj = 0; jj < 4; jj++) s2[ii][jj] = 0ull;

                #pragma unroll 4
                for (int k4 = 0; k4 < 64; k4++) {
                    ulonglong2 q[4], kk[4];
                    #pragma unroll
                    for (int ii = 0; ii < 4; ii++)
                        q[ii] = *(const ulonglong2*)(qrow[ii] + ((k4 ^ qsw[ii]) << 2));
                    #pragma unroll
                    for (int jj = 0; jj < 4; jj++)
                        kk[jj] = *(const ulonglong2*)(krow[jj] + ((k4 ^ ksw[jj]) << 2));
                    #pragma unroll
                    for (int ii = 0; ii < 4; ii++)
                        #pragma unroll
                        for (int jj = 0; jj < 4; jj++) {
                            s2[ii][jj] = ffma2(q[ii].x, kk[jj].x, s2[ii][jj]);
                            s2[ii][jj] = ffma2(q[ii].y, kk[jj].y, s2[ii][jj]);
                        }
                }
                #pragma unroll
                for (int ii = 0; ii < 4; ii++) {
                    float2 a0 = funpack(s2[ii][0]);
                    float2 a1 = funpack(s2[ii][1]);
                    float2 a2 = funpack(s2[ii][2]);
                    float2 a3 = funpack(s2[ii][3]);
                    float4 sv = make_float4(a0.x + a0.y, a1.x + a1.y,
                                            a2.x + a2.y, a3.x + a3.y);
                    *(float4*)&Ps[(i0 + ii) * PP + j0] = sv;
                }
            }
            __syncthreads();   // all warps done reading Ks

            // ---- async-load V into the K buffer ----
            const float4* Vg = (const float4*)(g_V + ((size_t)b * HW + kt * NTK) * CH);
            #pragma unroll
            for (int r = 0; r < 32; r++) {
                int e = tid + 256 * r;
                int row = e >> 6, g = e & 63;
                cpa16(KsA + (unsigned int)SWZ(row, g) * 16u, Vg + (size_t)row * 64 + g);
            }
            cpa_commit();

            // ---- warp-local online softmax over this warp's 8 rows ----
            __syncwarp();
            #pragma unroll
            for (int rr = 0; rr < 8; rr++) {
                float* pr = &Ps[(wid * 8 + rr) * PP + lane];
                float s0 = pr[0], s1 = pr[32], s2v = pr[64], s3 = pr[96];
                float mx = fmaxf(fmaxf(s0, s1), fmaxf(s2v, s3));
                #pragma unroll
                for (int o = 16; o; o >>= 1) mx = fmaxf(mx, __shfl_xor_sync(~0u, mx, o));
                float mn   = fmaxf(m8[rr], mx);
                float corr = __expf(m8[rr] - mn);
                float e0 = __expf(s0 - mn), e1 = __expf(s1 - mn);
                float e2 = __expf(s2v - mn), e3 = __expf(s3 - mn);
                float rs = (e0 + e1) + (e2 + e3);
                #pragma unroll
                for (int o = 16; o; o >>= 1) rs += __shfl_xor_sync(~0u, rs, o);
                l8[rr] = l8[rr] * corr + rs;
                m8[rr] = mn;
                pr[0] = e0; pr[32] = e1; pr[64] = e2; pr[96] = e3;
                unsigned long long c2 = fpack2(corr);
                #pragma unroll
                for (int u = 0; u < 4; u++) {
                    O1[rr][u] = fmul2(O1[rr][u], c2);
                    O2[rr][u] = fmul2(O2[rr][u], c2);
                }
            }

            cpa_wait0();
            __syncthreads();   // V ready; all P final

            // ---- P @ [V, V^2], packed accumulators ----
            const float* Pw = &Ps[(wid * 8) * PP];
            #pragma unroll 2
            for (int j = 0; j < NTK; j++) {
                int sw = (j >> 3) & 7;
                const float* vb = Ks + (j << 8);
                ulonglong2 va = *(const ulonglong2*)(vb + (((2 * lane)     ^ sw) << 2));
                ulonglong2 vbq = *(const ulonglong2*)(vb + (((2 * lane + 1) ^ sw) << 2));
                unsigned long long q0 = fmul2(va.x, va.x);
                unsigned long long q1 = fmul2(va.y, va.y);
                unsigned long long q2 = fmul2(vbq.x, vbq.x);
                unsigned long long q3 = fmul2(vbq.y, vbq.y);
                #pragma unroll
                for (int rr = 0; rr < 8; rr++) {
                    unsigned long long pp = fpack2(Pw[rr * PP + j]);
                    O1[rr][0] = ffma2(pp, va.x,  O1[rr][0]);
                    O1[rr][1] = ffma2(pp, va.y,  O1[rr][1]);
                    O1[rr][2] = ffma2(pp, vbq.x, O1[rr][2]);
                    O1[rr][3] = ffma2(pp, vbq.y, O1[rr][3]);
                    O2[rr][0] = ffma2(pp, q0, O2[rr][0]);
                    O2[rr][1] = ffma2(pp, q1, O2[rr][1]);
                    O2[rr][2] = ffma2(pp, q2, O2[rr][2]);
                    O2[rr][3] = ffma2(pp, q3, O2[rr][3]);
                }
            }
        }

        // ---- epilogue ----
        const size_t TSZ = (size_t)NB * CH * HW;
        int boff = b * CH;
        #pragma unroll
        for (int rr = 0; rr < 8; rr++) {
            int p = p0 + wid * 8 + rr;
            float rn = 1.0f / l8[rr];
            #pragma unroll
            for (int u = 0; u < 4; u++) {
                float2 o1 = funpack(O1[rr][u]);
                float2 o2 = funpack(O2[rr][u]);
                #pragma unroll
                for (int h = 0; h < 2; h++) {
                    int c = d0 + u * 2 + h;
                    float mean = (h ? o1.y : o1.x) * rn;
                    float sec  = (h ? o2.y : o2.x) * rn;
                    float sd   = sqrtf(fmaxf(sec - mean * mean, 0.f));
                    size_t idx = (size_t)(boff + c) * HW + p;
                    float nc = (content[idx] - g_mean[boff + c]) * g_rstd[boff + c];
                    out[idx]           = sd * nc + mean;
                    out[idx + TSZ]     = mean;
                    out[idx + 2 * TSZ] = sd;
                }
            }
        }
    }
}

// =====================================================================
extern "C" void kernel_launch(void* const* d_in, const int* in_sizes, int n_in,
                              void* d_out, int out_size) {
    const float* content = (const float*)d_in[0];
    const float* style   = (const float*)d_in[1];
    const float* Wf = (const float*)d_in[2];
    const float* bf = (const float*)d_in[3];
    const float* Wg = (const float*)d_in[4];
    const float* bg = (const float*)d_in[5];
    const float* Wh = (const float*)d_in[6];
    const float* bh = (const float*)d_in[7];
    float* out = (float*)d_out;

    stats_kernel<<<2 * NBC, 256>>>(content, style);
    qkv_gemm<<<dim3(HW / 128, CH / 64, 3 * NB), 256>>>(content, style,
                                                       Wf, bf, Wg, bg, Wh, bh);
    const int smem = (MQ * CH + NTK * CH + MQ * PP) * (int)sizeof(float);
    static bool attr_set = false;
    if (!attr_set) {
        cudaFuncSetAttribute(attn_kernel,
                             cudaFuncAttributeMaxDynamicSharedMemorySize, smem);
        attr_set = true;
    }
    attn_kernel<<<dim3(HW / (2 * MQ), NB), 256, smem>>>(content, out);
}